// round 4
// baseline (speedup 1.0000x reference)
#include <cuda_runtime.h>
#include <cstdint>

// ---------------------------------------------------------------------------
// DynamicConvBlock: fused 65-tap combined depthwise conv + ReLU + 1x1 conv.
//   x:(8,192,96,96) f32 -> out:(8,64,96,96) f32
// Stage 1: conv kernel. Folds 7 weight tensors + a[] into a 65-tap table in
//          smem; streaming-window depthwise conv, 2 channels per f32x2.
//          Division-free vectorized halo load.
// Stage 2: pointwise 1x1 conv 192->64. Pixel-pair f32x2 packing, weights
//          pre-duplicated (w,w) in smem -> zero packing movs in hot loop.
//          8 px x 4 oc per thread, 32 warps/SM.
// ---------------------------------------------------------------------------

#define NB   8
#define NC   192
#define NCP  96          // channel pairs
#define NH   96
#define NW   96
#define HW   (NH*NW)     // 9216
#define NOC  64
#define TAPS 65
#define PROW 16          // output rows per thread in conv kernel

// scratch (device globals are the sanctioned scratch mechanism)
__device__ float g_mid[(size_t)NB * NC * HW];         // relu'd depthwise output (56.6 MB)

// ---- tap tables (section = one dx column; dy list per section) -------------
__device__ constexpr int SEC_DX[11]   = {-7,-5,-3,-2,-1, 0, 1, 2, 3, 5, 7};
__device__ constexpr int SEC_BASE[11] = {-7,-5,-3,-3,-3,-7,-3,-3,-3,-5,-7};  // min dy
__device__ constexpr int SEC_W[11]    = {30,26,22,22,22,30,22,22,22,26,30};  // window rows (PROW + span)
__device__ constexpr int SEC_N[11]    = { 3, 3, 7, 7, 7,11, 7, 7, 7, 3, 3};
__device__ constexpr int SEC_OFF[11]  = { 0, 3, 6,13,20,27,38,45,52,59,62};

__device__ constexpr int DY_FLAT[TAPS] = {
    -7,0,7,
    -5,0,5,
    -3,-2,-1,0,1,2,3,
    -3,-2,-1,0,1,2,3,
    -3,-2,-1,0,1,2,3,
    -7,-5,-3,-2,-1,0,1,2,3,5,7,
    -3,-2,-1,0,1,2,3,
    -3,-2,-1,0,1,2,3,
    -3,-2,-1,0,1,2,3,
    -5,0,5,
    -7,0,7
};
__device__ constexpr int DX_FLAT[TAPS] = {
    -7,-7,-7,
    -5,-5,-5,
    -3,-3,-3,-3,-3,-3,-3,
    -2,-2,-2,-2,-2,-2,-2,
    -1,-1,-1,-1,-1,-1,-1,
     0, 0, 0, 0, 0, 0, 0, 0, 0, 0, 0,
     1, 1, 1, 1, 1, 1, 1,
     2, 2, 2, 2, 2, 2, 2,
     3, 3, 3, 3, 3, 3, 3,
     5, 5, 5,
     7, 7, 7
};

// ---- packed f32x2 helpers --------------------------------------------------
__device__ __forceinline__ unsigned long long fma2_(unsigned long long a,
                                                    unsigned long long b,
                                                    unsigned long long c) {
    unsigned long long d;
    asm("fma.rn.f32x2 %0, %1, %2, %3;" : "=l"(d) : "l"(a), "l"(b), "l"(c));
    return d;
}
__device__ __forceinline__ float2 unpk2_(unsigned long long v) {
    float2 f;
    asm("mov.b64 {%0, %1}, %2;" : "=f"(f.x), "=f"(f.y) : "l"(v));
    return f;
}

// ---- fold the 7 weight tensors + a[] into one 65-tap weight ----------------
__device__ __forceinline__ float fold_weight(int c, int t,
                                             const float* __restrict__ a,
                                             const float* __restrict__ k1,
                                             const float* __restrict__ k3,
                                             const float* __restrict__ k5,
                                             const float* __restrict__ k7,
                                             const float* __restrict__ k3d5,
                                             const float* __restrict__ k3d7) {
    int dy = DY_FLAT[t], dx = DX_FLAT[t];
    float w = 0.0f;
    if (abs(dy) <= 3 && abs(dx) <= 3) w += a[4] * k7[c * 49 + (dy + 3) * 7 + (dx + 3)];
    if (abs(dy) <= 2 && abs(dx) <= 2) w += a[3] * k5[c * 25 + (dy + 2) * 5 + (dx + 2)];
    if (abs(dy) <= 1 && abs(dx) <= 1) w += (a[2] + a[5]) * k3[c * 9 + (dy + 1) * 3 + (dx + 1)];
    if (dy == 0 && dx == 0)           w += a[0] + a[1] * k1[c];
    if ((dy == -5 || dy == 0 || dy == 5) && (dx == -5 || dx == 0 || dx == 5))
        w += a[6] * k3d5[c * 9 + (dy / 5 + 1) * 3 + (dx / 5 + 1)];
    if ((dy == -7 || dy == 0 || dy == 7) && (dx == -7 || dx == 0 || dx == 7))
        w += a[7] * k3d7[c * 9 + (dy / 7 + 1) * 3 + (dx / 7 + 1)];
    return w;
}

// ---------------------------------------------------------------------------
// Stage 1: depthwise conv + ReLU. One block = (batch, channel-pair, 16-row
// strip across full width). 96 threads, one image column each, 16 rows each.
// ---------------------------------------------------------------------------
#define SM_ROWS 30
#define SM_PITCH 112   // float2 units, >= 110

__global__ void __launch_bounds__(96)
conv_kernel(const float* __restrict__ x,
            const float* __restrict__ a,
            const float* __restrict__ k1,
            const float* __restrict__ k3,
            const float* __restrict__ k5,
            const float* __restrict__ k7,
            const float* __restrict__ k3d5,
            const float* __restrict__ k3d7) {
    __shared__ float2 sm[SM_ROWS][SM_PITCH];
    __shared__ float2 sw[TAPS];

    const int tid = threadIdx.x;                    // 0..95
    const int bc  = blockIdx.y;                     // b*96 + cp
    const int b   = bc / NCP;
    const int cp  = bc - b * NCP;
    const int c0  = cp * 2;
    const int h0  = blockIdx.x * PROW;              // 0,16,...,80

    // ---- zero entire smem tile (vectorized, division-free) ----
    {
        float4* smf = reinterpret_cast<float4*>(&sm[0][0]);   // 30*112/2 = 1680 float4
        for (int i = tid; i < SM_ROWS * SM_PITCH / 2; i += 96)
            smf[i] = make_float4(0.f, 0.f, 0.f, 0.f);
    }

    // ---- fold combined weights for this channel pair into smem ----
    for (int i = tid; i < 2 * TAPS; i += 96) {
        int t = i >> 1, half = i & 1;
        float w = fold_weight(c0 + half, t, a, k1, k3, k5, k7, k3d5, k3d7);
        reinterpret_cast<float*>(&sw[t])[half] = w;
    }
    __syncthreads();

    // ---- interior halo rows: thread = one coalesced column ----
    const size_t xbase = ((size_t)b * NC + c0) * HW;
    {
        const int r0 = (h0 >= 7)      ? 0  : 7 - h0;          // first valid smem row
        const int r1 = (h0 <= NH - 23)? 30 : (NH + 7 - h0);   // one past last valid
        const float* px0 = x + xbase + (size_t)(h0 - 7) * NW + tid;
        for (int r = r0; r < r1; r++) {
            float2 v;
            v.x = px0[(size_t)r * NW];
            v.y = px0[(size_t)r * NW + HW];
            sm[r][tid + 7] = v;
        }
    }
    __syncthreads();

    const int col = tid + 7;                         // smem column of this thread
    const unsigned long long* swq = reinterpret_cast<const unsigned long long*>(sw);

    unsigned long long acc[PROW];
#pragma unroll
    for (int p = 0; p < PROW; p++) acc[p] = 0ull;

#pragma unroll
    for (int s = 0; s < 11; s++) {
        const int bse = SEC_BASE[s];
        const int wl  = SEC_W[s];
        const int nd  = SEC_N[s];
        const int off = SEC_OFF[s];
        const int cx  = col + SEC_DX[s];

        // preload this section's weights (<=11 pairs) into registers
        unsigned long long wv[11];
#pragma unroll
        for (int j = 0; j < nd; j++) wv[j] = swq[off + j];

        // stream window rows: one live input value at a time
#pragma unroll
        for (int i = 0; i < wl; i++) {
            unsigned long long v =
                *reinterpret_cast<const unsigned long long*>(&sm[bse + 7 + i][cx]);
#pragma unroll
            for (int j = 0; j < nd; j++) {
                const int p = i - (DY_FLAT[off + j] - bse);   // compile-time
                if (p >= 0 && p < PROW)
                    acc[p] = fma2_(v, wv[j], acc[p]);
            }
        }
    }

    // ---- ReLU + store to g_mid (standard NCHW layout) ----
    float* m0 = g_mid + xbase + (size_t)h0 * NW + tid;
#pragma unroll
    for (int p = 0; p < PROW; p++) {
        float2 v = unpk2_(acc[p]);
        v.x = fmaxf(v.x, 0.0f);
        v.y = fmaxf(v.y, 0.0f);
        m0[(size_t)p * NW]      = v.x;
        m0[(size_t)p * NW + HW] = v.y;
    }
}

// ---------------------------------------------------------------------------
// Stage 2: pointwise 1x1 conv 192->64.
// Pixel-pair f32x2 packing: mid float4 loads ARE the FMA2 A-operands;
// weights pre-duplicated (w,w) in smem so broadcast LDS.64 IS the B-operand.
// Thread = 8 px x 4 oc (acc = 16 pairs = 32 regs).
// Block = 128 thr = 32 pxg x 4 ocg -> 256 px, 16 oc. Grid = 288 x 4 oc-qtrs.
// smem 24.5 KB -> 8 blocks/SM, 32 warps.
// ---------------------------------------------------------------------------
__global__ void __launch_bounds__(128)
pointwise_kernel(const float* __restrict__ wp, float* __restrict__ out) {
    __shared__ float2 ws[NC * 16];                  // ws[c*16+j] = dup(wp[ocq*16+j][c])

    const int tid = threadIdx.x;
    const int bx  = blockIdx.x;
    const int ocq = bx & 3;                          // oc quarter (16 oc)
    const int pxb = bx >> 2;                         // pixel block (256 px)

    for (int i = tid; i < NC * 16; i += 128) {
        int c = i >> 4, j = i & 15;
        float w = wp[(ocq * 16 + j) * NC + c];
        ws[i] = make_float2(w, w);
    }
    __syncthreads();

    const int pxg = tid & 31;                        // 0..31
    const int ocg = tid >> 5;                        // 0..3, uniform per warp
    const int pixglob = pxb * 256 + pxg * 8;         // 256 | 9216
    const int b   = pixglob / HW;
    const int pix = pixglob - b * HW;

    const float* midb = g_mid + (size_t)b * NC * HW + pix;
    const unsigned long long* wbase =
        reinterpret_cast<const unsigned long long*>(ws) + ocg * 4;

    unsigned long long acc[4][4];                    // [oc][px-pair]
#pragma unroll
    for (int j = 0; j < 4; j++)
#pragma unroll
        for (int q = 0; q < 4; q++) acc[j][q] = 0ull;

#pragma unroll 2
    for (int c = 0; c < NC; c++) {
        const unsigned long long* mrow =
            reinterpret_cast<const unsigned long long*>(midb + (size_t)c * HW);
        // two 16B loads = 4 px-pairs, directly FMA2-ready
        unsigned long long m0, m1, m2, m3;
        {
            ulonglong2 t0 = *reinterpret_cast<const ulonglong2*>(mrow);
            ulonglong2 t1 = *reinterpret_cast<const ulonglong2*>(mrow + 2);
            m0 = t0.x; m1 = t0.y; m2 = t1.x; m3 = t1.y;
        }
        const unsigned long long* wr = wbase + c * 16;
#pragma unroll
        for (int j = 0; j < 4; j++) {
            unsigned long long w2 = wr[j];           // broadcast LDS.64, pre-dup'd
            acc[j][0] = fma2_(m0, w2, acc[j][0]);
            acc[j][1] = fma2_(m1, w2, acc[j][1]);
            acc[j][2] = fma2_(m2, w2, acc[j][2]);
            acc[j][3] = fma2_(m3, w2, acc[j][3]);
        }
    }

    // out[((b*64 + ocq*16 + ocg*4 + j) * HW) + pix + 0..7], px order preserved
    float* ob = out + ((size_t)b * NOC + ocq * 16 + ocg * 4) * HW + pix;
#pragma unroll
    for (int j = 0; j < 4; j++) {
        ulonglong2 lo, hi;
        lo.x = acc[j][0]; lo.y = acc[j][1];
        hi.x = acc[j][2]; hi.y = acc[j][3];
        *reinterpret_cast<ulonglong2*>(ob + (size_t)j * HW)     = lo;
        *reinterpret_cast<ulonglong2*>(ob + (size_t)j * HW + 4) = hi;
    }
}

// ---------------------------------------------------------------------------
extern "C" void kernel_launch(void* const* d_in, const int* in_sizes, int n_in,
                              void* d_out, int out_size) {
    const float* x    = (const float*)d_in[0];   // 8*192*96*96
    const float* a    = (const float*)d_in[1];   // 8
    const float* k1   = (const float*)d_in[2];   // 192*1*1*1
    const float* k3   = (const float*)d_in[3];   // 192*1*3*3
    const float* k5   = (const float*)d_in[4];   // 192*1*5*5
    const float* k7   = (const float*)d_in[5];   // 192*1*7*7
    const float* k3d5 = (const float*)d_in[6];   // 192*1*3*3
    const float* k3d7 = (const float*)d_in[7];   // 192*1*3*3
    const float* wp   = (const float*)d_in[8];   // 64*192*1*1
    float* out = (float*)d_out;

    conv_kernel<<<dim3(NH / PROW, NB * NCP), 96>>>(x, a, k1, k3, k5, k7, k3d5, k3d7);
    pointwise_kernel<<<dim3((NB * HW / 256) * 4), 128>>>(wp, out);
}

// round 6
// speedup vs baseline: 1.3378x; 1.3378x over previous
#include <cuda_runtime.h>
#include <cstdint>

// ---------------------------------------------------------------------------
// DynamicConvBlock: fused 65-tap combined depthwise conv + ReLU + 1x1 conv.
//   x:(8,192,96,96) f32 -> out:(8,64,96,96) f32
// Stage 0: prep_w transposes + duplicates wp into g_wdup[(c,oc)] = (w,w).
// Stage 1: conv kernel (unchanged from R4: streaming window, f32x2 pairs,
//          division-free halo load) -> g_mid. ~31us, near FFMA2 floor.
// Stage 2: pointwise v3: cp.async double-buffered smem GEMM, 256px x 64oc
//          per block, px-pair FFMA2 with pre-duplicated weights.
// ---------------------------------------------------------------------------

#define NB   8
#define NC   192
#define NCP  96
#define NH   96
#define NW   96
#define HW   (NH*NW)     // 9216
#define NOC  64
#define TAPS 65
#define PROW 16

// scratch
__device__ float  g_mid[(size_t)NB * NC * HW];     // 56.6 MB
__device__ float2 g_wdup[NC * NOC];                // 96 KB, (w,w) dup'd, [c][oc]

// ---- tap tables ------------------------------------------------------------
__device__ constexpr int SEC_DX[11]   = {-7,-5,-3,-2,-1, 0, 1, 2, 3, 5, 7};
__device__ constexpr int SEC_BASE[11] = {-7,-5,-3,-3,-3,-7,-3,-3,-3,-5,-7};
__device__ constexpr int SEC_W[11]    = {30,26,22,22,22,30,22,22,22,26,30};
__device__ constexpr int SEC_N[11]    = { 3, 3, 7, 7, 7,11, 7, 7, 7, 3, 3};
__device__ constexpr int SEC_OFF[11]  = { 0, 3, 6,13,20,27,38,45,52,59,62};

__device__ constexpr int DY_FLAT[TAPS] = {
    -7,0,7,
    -5,0,5,
    -3,-2,-1,0,1,2,3,
    -3,-2,-1,0,1,2,3,
    -3,-2,-1,0,1,2,3,
    -7,-5,-3,-2,-1,0,1,2,3,5,7,
    -3,-2,-1,0,1,2,3,
    -3,-2,-1,0,1,2,3,
    -3,-2,-1,0,1,2,3,
    -5,0,5,
    -7,0,7
};
__device__ constexpr int DX_FLAT[TAPS] = {
    -7,-7,-7,
    -5,-5,-5,
    -3,-3,-3,-3,-3,-3,-3,
    -2,-2,-2,-2,-2,-2,-2,
    -1,-1,-1,-1,-1,-1,-1,
     0, 0, 0, 0, 0, 0, 0, 0, 0, 0, 0,
     1, 1, 1, 1, 1, 1, 1,
     2, 2, 2, 2, 2, 2, 2,
     3, 3, 3, 3, 3, 3, 3,
     5, 5, 5,
     7, 7, 7
};

// ---- packed f32x2 helpers --------------------------------------------------
__device__ __forceinline__ unsigned long long fma2_(unsigned long long a,
                                                    unsigned long long b,
                                                    unsigned long long c) {
    unsigned long long d;
    asm("fma.rn.f32x2 %0, %1, %2, %3;" : "=l"(d) : "l"(a), "l"(b), "l"(c));
    return d;
}
__device__ __forceinline__ float2 unpk2_(unsigned long long v) {
    float2 f;
    asm("mov.b64 {%0, %1}, %2;" : "=f"(f.x), "=f"(f.y) : "l"(v));
    return f;
}
__device__ __forceinline__ void cpasync16(uint32_t dst, const void* src) {
    asm volatile("cp.async.cg.shared.global [%0], [%1], 16;" :: "r"(dst), "l"(src));
}
__device__ __forceinline__ void cpcommit() {
    asm volatile("cp.async.commit_group;");
}

// ---- fold the 7 weight tensors + a[] into one 65-tap weight ----------------
__device__ __forceinline__ float fold_weight(int c, int t,
                                             const float* __restrict__ a,
                                             const float* __restrict__ k1,
                                             const float* __restrict__ k3,
                                             const float* __restrict__ k5,
                                             const float* __restrict__ k7,
                                             const float* __restrict__ k3d5,
                                             const float* __restrict__ k3d7) {
    int dy = DY_FLAT[t], dx = DX_FLAT[t];
    float w = 0.0f;
    if (abs(dy) <= 3 && abs(dx) <= 3) w += a[4] * k7[c * 49 + (dy + 3) * 7 + (dx + 3)];
    if (abs(dy) <= 2 && abs(dx) <= 2) w += a[3] * k5[c * 25 + (dy + 2) * 5 + (dx + 2)];
    if (abs(dy) <= 1 && abs(dx) <= 1) w += (a[2] + a[5]) * k3[c * 9 + (dy + 1) * 3 + (dx + 1)];
    if (dy == 0 && dx == 0)           w += a[0] + a[1] * k1[c];
    if ((dy == -5 || dy == 0 || dy == 5) && (dx == -5 || dx == 0 || dx == 5))
        w += a[6] * k3d5[c * 9 + (dy / 5 + 1) * 3 + (dx / 5 + 1)];
    if ((dy == -7 || dy == 0 || dy == 7) && (dx == -7 || dx == 0 || dx == 7))
        w += a[7] * k3d7[c * 9 + (dy / 7 + 1) * 3 + (dx / 7 + 1)];
    return w;
}

// ---------------------------------------------------------------------------
// Stage 0: transpose + duplicate wp -> g_wdup[c*64+oc] = (w,w)
// ---------------------------------------------------------------------------
__global__ void prep_w(const float* __restrict__ wp) {
    int i = blockIdx.x * 256 + threadIdx.x;
    if (i < NC * NOC) {
        int c = i >> 6, oc = i & 63;
        float w = wp[oc * NC + c];
        g_wdup[i] = make_float2(w, w);
    }
}

// ---------------------------------------------------------------------------
// Stage 1: depthwise conv + ReLU (unchanged from R4).
// ---------------------------------------------------------------------------
#define SM_ROWS 30
#define SM_PITCH 112

__global__ void __launch_bounds__(96)
conv_kernel(const float* __restrict__ x,
            const float* __restrict__ a,
            const float* __restrict__ k1,
            const float* __restrict__ k3,
            const float* __restrict__ k5,
            const float* __restrict__ k7,
            const float* __restrict__ k3d5,
            const float* __restrict__ k3d7) {
    __shared__ float2 sm[SM_ROWS][SM_PITCH];
    __shared__ float2 sw[TAPS];

    const int tid = threadIdx.x;
    const int bc  = blockIdx.y;
    const int b   = bc / NCP;
    const int cp  = bc - b * NCP;
    const int c0  = cp * 2;
    const int h0  = blockIdx.x * PROW;

    {
        float4* smf = reinterpret_cast<float4*>(&sm[0][0]);
        for (int i = tid; i < SM_ROWS * SM_PITCH / 2; i += 96)
            smf[i] = make_float4(0.f, 0.f, 0.f, 0.f);
    }

    for (int i = tid; i < 2 * TAPS; i += 96) {
        int t = i >> 1, half = i & 1;
        float w = fold_weight(c0 + half, t, a, k1, k3, k5, k7, k3d5, k3d7);
        reinterpret_cast<float*>(&sw[t])[half] = w;
    }
    __syncthreads();

    const size_t xbase = ((size_t)b * NC + c0) * HW;
    {
        const int r0 = (h0 >= 7)       ? 0  : 7 - h0;
        const int r1 = (h0 <= NH - 23) ? 30 : (NH + 7 - h0);
        const float* px0 = x + xbase + (size_t)(h0 - 7) * NW + tid;
        for (int r = r0; r < r1; r++) {
            float2 v;
            v.x = px0[(size_t)r * NW];
            v.y = px0[(size_t)r * NW + HW];
            sm[r][tid + 7] = v;
        }
    }
    __syncthreads();

    const int col = tid + 7;
    const unsigned long long* swq = reinterpret_cast<const unsigned long long*>(sw);

    unsigned long long acc[PROW];
#pragma unroll
    for (int p = 0; p < PROW; p++) acc[p] = 0ull;

#pragma unroll
    for (int s = 0; s < 11; s++) {
        const int bse = SEC_BASE[s];
        const int wl  = SEC_W[s];
        const int nd  = SEC_N[s];
        const int off = SEC_OFF[s];
        const int cx  = col + SEC_DX[s];

        unsigned long long wv[11];
#pragma unroll
        for (int j = 0; j < nd; j++) wv[j] = swq[off + j];

#pragma unroll
        for (int i = 0; i < wl; i++) {
            unsigned long long v =
                *reinterpret_cast<const unsigned long long*>(&sm[bse + 7 + i][cx]);
#pragma unroll
            for (int j = 0; j < nd; j++) {
                const int p = i - (DY_FLAT[off + j] - bse);
                if (p >= 0 && p < PROW)
                    acc[p] = fma2_(v, wv[j], acc[p]);
            }
        }
    }

    float* m0 = g_mid + xbase + (size_t)h0 * NW + tid;
#pragma unroll
    for (int p = 0; p < PROW; p++) {
        float2 v = unpk2_(acc[p]);
        v.x = fmaxf(v.x, 0.0f);
        v.y = fmaxf(v.y, 0.0f);
        m0[(size_t)p * NW]      = v.x;
        m0[(size_t)p * NW + HW] = v.y;
    }
}

// ---------------------------------------------------------------------------
// Stage 2: pointwise v3. Block = 256 px x 64 oc, 256 threads.
// K split into 24 chunks of 8 channels, cp.async double-buffered.
//   midbuf[buf]: 8c x 256px floats          (8 KB each)
//   wbuf[buf]:   8 ocg x (8c x 16+pad) words, dup'd weights, bank-padded
// Thread = 8 px (4 f32x2 pairs) x 8 oc. acc = 32 f32x2.
// Hot loop per c: 2 LDS.128 (px) + 4 LDS.128 (dup'd w) + 32 FFMA2.
// ---------------------------------------------------------------------------
#define CHUNK   8
#define NCHUNK  (NC / CHUNK)          // 24
#define WSTRIDE 132                    // words per ocg: 8c*16 + 4 pad

__global__ void __launch_bounds__(256)
pointwise_kernel(float* __restrict__ out) {
    __shared__ float midbuf[2][CHUNK * 256];            // 2 x 8KB
    __shared__ float wbuf[2][8 * WSTRIDE];              // 2 x 4.2KB

    const int tid = threadIdx.x;
    const int pixglob = blockIdx.x * 256;               // 256 | 9216
    const int b   = pixglob / HW;
    const int pix = pixglob - b * HW;

    const float* midb = g_mid + (size_t)b * NC * HW + pix;

    const int ocg = tid & 7;                            // 8 oc per group
    const int pxg = tid >> 3;                           // 32 groups x 8 px

    // staging index precompute (mid: 2 x 16B per thread; w: 1 x 16B)
    const int mc0 = tid >> 6, moff0 = (tid & 63) * 4;           // i = tid
    const int mc1 = (tid + 256) >> 6, moff1 = (tid & 63) * 4;   // i = tid+256
    const int wg  = tid >> 5;                                    // ocg slot
    const int wr  = tid & 31;
    const int wc  = wr >> 2, wq = wr & 3;

    uint32_t mid_s0 = (uint32_t)__cvta_generic_to_shared(&midbuf[0][0]);
    uint32_t mid_s1 = (uint32_t)__cvta_generic_to_shared(&midbuf[1][0]);
    uint32_t w_s0   = (uint32_t)__cvta_generic_to_shared(&wbuf[0][0]);
    uint32_t w_s1   = (uint32_t)__cvta_generic_to_shared(&wbuf[1][0]);

    auto stage = [&](int kc, int bsel) {
        uint32_t ms = bsel ? mid_s1 : mid_s0;
        uint32_t wsd = bsel ? w_s1 : w_s0;
        const int cbase = kc * CHUNK;
        cpasync16(ms + (uint32_t)(mc0 * 256 + moff0) * 4,
                  midb + (size_t)(cbase + mc0) * HW + moff0);
        cpasync16(ms + (uint32_t)(mc1 * 256 + moff1) * 4,
                  midb + (size_t)(cbase + mc1) * HW + moff1);
        cpasync16(wsd + (uint32_t)(wg * WSTRIDE + wc * 16 + wq * 4) * 4,
                  reinterpret_cast<const float*>(g_wdup) +
                      ((size_t)(cbase + wc) * NOC + wg * 8 + wq * 2) * 2);
    };

    unsigned long long acc[8][4];
#pragma unroll
    for (int j = 0; j < 8; j++)
#pragma unroll
        for (int q = 0; q < 4; q++) acc[j][q] = 0ull;

    stage(0, 0); cpcommit();
    stage(1, 1); cpcommit();

#pragma unroll 1
    for (int k = 0; k < NCHUNK; k++) {
        if (k < NCHUNK - 1) asm volatile("cp.async.wait_group 1;");
        else                asm volatile("cp.async.wait_group 0;");
        __syncthreads();

        const int bsel = k & 1;
        const float* mbase = &midbuf[bsel][pxg * 8];
        const float* wbase = &wbuf[bsel][ocg * WSTRIDE];

#pragma unroll
        for (int c = 0; c < CHUNK; c++) {
            const float* mrow = mbase + c * 256;
            ulonglong2 a01 = *reinterpret_cast<const ulonglong2*>(mrow);
            ulonglong2 a23 = *reinterpret_cast<const ulonglong2*>(mrow + 4);
            const float* wrow = wbase + c * 16;
            ulonglong2 w01 = *reinterpret_cast<const ulonglong2*>(wrow);
            ulonglong2 w23 = *reinterpret_cast<const ulonglong2*>(wrow + 4);
            ulonglong2 w45 = *reinterpret_cast<const ulonglong2*>(wrow + 8);
            ulonglong2 w67 = *reinterpret_cast<const ulonglong2*>(wrow + 12);

            unsigned long long wv[8] = {w01.x, w01.y, w23.x, w23.y,
                                        w45.x, w45.y, w67.x, w67.y};
#pragma unroll
            for (int j = 0; j < 8; j++) {
                acc[j][0] = fma2_(a01.x, wv[j], acc[j][0]);
                acc[j][1] = fma2_(a01.y, wv[j], acc[j][1]);
                acc[j][2] = fma2_(a23.x, wv[j], acc[j][2]);
                acc[j][3] = fma2_(a23.y, wv[j], acc[j][3]);
            }
        }
        __syncthreads();

        if (k + 2 < NCHUNK) { stage(k + 2, bsel); cpcommit(); }
    }

    // epilogue: out[b][ocg*8+j][pix + pxg*8 + 0..7]
    float* ob = out + ((size_t)b * NOC + ocg * 8) * HW + pix + pxg * 8;
#pragma unroll
    for (int j = 0; j < 8; j++) {
        ulonglong2 lo, hi;
        lo.x = acc[j][0]; lo.y = acc[j][1];
        hi.x = acc[j][2]; hi.y = acc[j][3];
        *reinterpret_cast<ulonglong2*>(ob + (size_t)j * HW)     = lo;
        *reinterpret_cast<ulonglong2*>(ob + (size_t)j * HW + 4) = hi;
    }
}

// ---------------------------------------------------------------------------
extern "C" void kernel_launch(void* const* d_in, const int* in_sizes, int n_in,
                              void* d_out, int out_size) {
    const float* x    = (const float*)d_in[0];
    const float* a    = (const float*)d_in[1];
    const float* k1   = (const float*)d_in[2];
    const float* k3   = (const float*)d_in[3];
    const float* k5   = (const float*)d_in[4];
    const float* k7   = (const float*)d_in[5];
    const float* k3d5 = (const float*)d_in[6];
    const float* k3d7 = (const float*)d_in[7];
    const float* wp   = (const float*)d_in[8];
    float* out = (float*)d_out;

    prep_w<<<(NC * NOC + 255) / 256, 256>>>(wp);
    conv_kernel<<<dim3(NH / PROW, NB * NCP), 96>>>(x, a, k1, k3, k5, k7, k3d5, k3d7);
    pointwise_kernel<<<NB * HW / 256, 256>>>(out);
}